// round 6
// baseline (speedup 1.0000x reference)
#include <cuda_runtime.h>
#include <cstdint>

// GRU decoder (Keras reset_after=True), B=32768, T=48, F=16, H=32, fp32.
// Lane j owns neuron j. f32x2 pairs run over the REDUCTION index k, so the
// weight operand {w[k],w[k+1]} is naturally contiguous in registers — no
// per-use duplication MOVs. Warp processes 4 batches; h and features are
// broadcast via per-warp shared buffers (LDS.128 = 2 k-pairs, 1 wavefront).

typedef unsigned long long u64;

namespace {
constexpr int kT     = 48;
constexpr int kF     = 16;
constexpr int kH     = 32;
constexpr int kTasks = 8192;             // 32768 batches / 4 per task
constexpr int kCTA   = 128;              // 4 warps
constexpr int kGrid  = 296;              // 1184 warps
constexpr int kWarps = kGrid * (kCTA / 32);
}

__device__ __forceinline__ u64 pack2(float lo, float hi) {
    u64 r; asm("mov.b64 %0, {%1, %2};" : "=l"(r) : "f"(lo), "f"(hi)); return r;
}
__device__ __forceinline__ void unpack2(u64 v, float& lo, float& hi) {
    asm("mov.b64 {%0, %1}, %2;" : "=f"(lo), "=f"(hi) : "l"(v));
}
__device__ __forceinline__ u64 fma2(u64 a, u64 b, u64 c) {
    u64 d; asm("fma.rn.f32x2 %0, %1, %2, %3;" : "=l"(d) : "l"(a), "l"(b), "l"(c)); return d;
}
__device__ __forceinline__ float ex2a(float x) {
    float r; asm("ex2.approx.f32 %0, %1;" : "=f"(r) : "f"(x)); return r;
}
__device__ __forceinline__ float rcpa(float x) {
    float r; asm("rcp.approx.f32 %0, %1;" : "=f"(r) : "f"(x)); return r;
}
__device__ __forceinline__ float sig_fast(float x) {   // exact saturation at +/-inf
    return rcpa(1.0f + ex2a(-1.4426950408889634f * x));
}
__device__ __forceinline__ float tanh_fast(float x) {
    return fmaf(-2.0f, rcpa(1.0f + ex2a(2.8853900817779268f * x)), 1.0f);
}
__device__ __forceinline__ uint32_t smem_u32(const void* p) {
    return (uint32_t)__cvta_generic_to_shared(p);
}
__device__ __forceinline__ void sts32(uint32_t a, float v) {
    asm volatile("st.shared.f32 [%0], %1;" :: "r"(a), "f"(v));
}
__device__ __forceinline__ void lds128(uint32_t a, u64& x, u64& y) {
    asm volatile("ld.shared.v2.u64 {%0,%1}, [%2];" : "=l"(x), "=l"(y) : "r"(a));
}
__device__ __forceinline__ float redsum(float v) {   // xor butterfly, all lanes get sum
#pragma unroll
    for (int m = 16; m >= 1; m >>= 1) v += __shfl_xor_sync(0xffffffffu, v, m);
    return v;
}

__global__ void __launch_bounds__(kCTA)
gru_decoder_kernel(const float* __restrict__ feat,      // [B,T,F]
                   const float* __restrict__ init_in,   // [B,1]
                   const float* __restrict__ init_h,    // [B,H]
                   const float* __restrict__ kern,      // [1+F, 3H]
                   const float* __restrict__ rker,      // [H, 3H]
                   const float* __restrict__ bx,        // [3H]
                   const float* __restrict__ bh,        // [3H]
                   const float* __restrict__ dw,        // [H,1]
                   const float* __restrict__ db,        // [1]
                   float* __restrict__ out)             // [B,T,1]
{
    // Per-warp broadcast buffers, double-buffered:
    // shH[w][buf][b][j] : hidden state of batch b (32 floats = 128 B row)
    // shX[w][buf][b][k] : features of batch b   (16 floats =  64 B row)
    __shared__ __align__(16) float shH[4][2][4][kH];
    __shared__ __align__(16) float shX[4][2][4][kF];

    const int tid  = threadIdx.x;
    const int wip  = tid >> 5;
    const int lane = tid & 31;

    // k-pair-packed weights (contiguous along k -> no dup MOVs at use site).
    u64 Rz2[kH / 2], Rr2[kH / 2], Rh2[kH / 2];
#pragma unroll
    for (int q = 0; q < kH / 2; q++) {
        Rz2[q] = pack2(rker[(2 * q) * 96 + lane],          rker[(2 * q + 1) * 96 + lane]);
        Rr2[q] = pack2(rker[(2 * q) * 96 + kH + lane],     rker[(2 * q + 1) * 96 + kH + lane]);
        Rh2[q] = pack2(rker[(2 * q) * 96 + 2 * kH + lane], rker[(2 * q + 1) * 96 + 2 * kH + lane]);
    }
    u64 Wz2[kF / 2], Wr2[kF / 2], Wx2[kF / 2];   // feature rows 1..16 of kern
#pragma unroll
    for (int q = 0; q < kF / 2; q++) {
        Wz2[q] = pack2(kern[(2 * q + 1) * 96 + lane],          kern[(2 * q + 2) * 96 + lane]);
        Wr2[q] = pack2(kern[(2 * q + 1) * 96 + kH + lane],     kern[(2 * q + 2) * 96 + kH + lane]);
        Wx2[q] = pack2(kern[(2 * q + 1) * 96 + 2 * kH + lane], kern[(2 * q + 2) * 96 + 2 * kH + lane]);
    }
    const float Wz0 = kern[lane];                 // prev_out row (kern row 0)
    const float Wr0 = kern[kH + lane];
    const float Wx0 = kern[2 * kH + lane];
    const float bz  = bx[lane] + bh[lane];
    const float br  = bx[kH + lane] + bh[kH + lane];
    const float bxv = bx[2 * kH + lane];
    const float bhv = bh[2 * kH + lane];
    const float dwl = dw[lane];
    const float dbv = db[0];

    const uint32_t baseH = smem_u32(&shH[wip][0][0][0]);
    const uint32_t baseX = smem_u32(&shX[wip][0][0][0]);

    const int wg = (blockIdx.x * kCTA + tid) >> 5;

#pragma unroll 1
    for (int task = wg; task < kTasks; task += kWarps) {
        const int b0 = 4 * task;

        float h[4], prev[4], fv[4];
#pragma unroll
        for (int b = 0; b < 4; b++) {
            h[b]    = init_h[(size_t)(b0 + b) * kH + lane];
            prev[b] = init_in[b0 + b];
            fv[b]   = 0.0f;
            if (lane < kF) fv[b] = feat[(size_t)(b0 + b) * kT * kF + lane];
        }

#pragma unroll 1
        for (int t = 0; t < kT; t++) {
            const uint32_t bufH = baseH + (uint32_t)(t & 1) * (4 * kH * 4);
            const uint32_t bufX = baseX + (uint32_t)(t & 1) * (4 * kF * 4);

            // Publish my state + staged features.
#pragma unroll
            for (int b = 0; b < 4; b++) {
                sts32(bufH + (uint32_t)(b * kH + lane) * 4, h[b]);
                if (lane < kF) sts32(bufX + (uint32_t)(b * kF + lane) * 4, fv[b]);
            }
            __syncwarp();

            // Load next step's features now (latency covered by mainloop).
            if (lane < kF) {
                int tn = (t + 1 < kT) ? t + 1 : t;
#pragma unroll
                for (int b = 0; b < 4; b++)
                    fv[b] = feat[(size_t)(b0 + b) * kT * kF + tn * kF + lane];
            }

            u64 az2[4], ar2[4], ah2[4], ax2[4];
#pragma unroll
            for (int b = 0; b < 4; b++) {
                az2[b] = 0ull; ar2[b] = 0ull; ah2[b] = 0ull; ax2[b] = 0ull;
            }

            // Recurrent part: broadcast LDS.128 = 2 k-pairs, feeds 3 gates.
#pragma unroll
            for (int q = 0; q < kH / 4; q++) {
#pragma unroll
                for (int b = 0; b < 4; b++) {
                    u64 p0, p1;
                    lds128(bufH + (uint32_t)(b * kH + 4 * q) * 4, p0, p1);
                    az2[b] = fma2(p0, Rz2[2 * q],     az2[b]);
                    ar2[b] = fma2(p0, Rr2[2 * q],     ar2[b]);
                    ah2[b] = fma2(p0, Rh2[2 * q],     ah2[b]);
                    az2[b] = fma2(p1, Rz2[2 * q + 1], az2[b]);
                    ar2[b] = fma2(p1, Rr2[2 * q + 1], ar2[b]);
                    ah2[b] = fma2(p1, Rh2[2 * q + 1], ah2[b]);
                }
            }
            // Feature part.
#pragma unroll
            for (int q = 0; q < kF / 4; q++) {
#pragma unroll
                for (int b = 0; b < 4; b++) {
                    u64 p0, p1;
                    lds128(bufX + (uint32_t)(b * kF + 4 * q) * 4, p0, p1);
                    az2[b] = fma2(p0, Wz2[2 * q],     az2[b]);
                    ar2[b] = fma2(p0, Wr2[2 * q],     ar2[b]);
                    ax2[b] = fma2(p0, Wx2[2 * q],     ax2[b]);
                    az2[b] = fma2(p1, Wz2[2 * q + 1], az2[b]);
                    ar2[b] = fma2(p1, Wr2[2 * q + 1], ar2[b]);
                    ax2[b] = fma2(p1, Wx2[2 * q + 1], ax2[b]);
                }
            }

            // Epilogue per batch: fold pairs, prev term, activations, output.
#pragma unroll
            for (int b = 0; b < 4; b++) {
                float lo, hi;
                unpack2(az2[b], lo, hi);
                float az = lo + hi + fmaf(Wz0, prev[b], bz);
                unpack2(ar2[b], lo, hi);
                float ar = lo + hi + fmaf(Wr0, prev[b], br);
                unpack2(ax2[b], lo, hi);
                float ax = lo + hi + fmaf(Wx0, prev[b], bxv);
                unpack2(ah2[b], lo, hi);
                float ah = lo + hi + bhv;

                float z = sig_fast(az);
                float r = sig_fast(ar);
                float hh = tanh_fast(fmaf(r, ah, ax));
                h[b] = fmaf(z, h[b] - hh, hh);

                float o = redsum(h[b] * dwl) + dbv;   // Dense(1), all lanes get o
                prev[b] = o;
                if (lane == 0) out[(size_t)(b0 + b) * kT + t] = o;
            }
        }
    }
}

extern "C" void kernel_launch(void* const* d_in, const int* in_sizes, int n_in,
                              void* d_out, int out_size) {
    (void)in_sizes; (void)n_in; (void)out_size;
    gru_decoder_kernel<<<kGrid, kCTA>>>(
        (const float*)d_in[0],   // decoder_feature
        (const float*)d_in[1],   // decoder_init_input
        (const float*)d_in[2],   // init_state
        (const float*)d_in[3],   // kernel
        (const float*)d_in[4],   // recurrent_kernel
        (const float*)d_in[5],   // bias_x
        (const float*)d_in[6],   // bias_h
        (const float*)d_in[7],   // dense_w
        (const float*)d_in[8],   // dense_b
        (float*)d_out);
}

// round 7
// speedup vs baseline: 1.0036x; 1.0036x over previous
#include <cuda_runtime.h>
#include <cstdint>

// GRU decoder (Keras reset_after=True), B=32768, T=48, F=16, H=32, fp32.
// Lane j owns neuron j; weights k-pair-packed in registers (f32x2 over the
// reduction index -> no dup MOVs). Warp runs 4 batches. h/features broadcast
// via per-warp shared buffers. The Dense(1) reduction for step t-1 is issued
// at the TOP of step t (operates on register h), so its 5-SHFL chain hides
// under the GEMM and the output-feedback leaves the critical path.

typedef unsigned long long u64;

namespace {
constexpr int kT     = 48;
constexpr int kF     = 16;
constexpr int kH     = 32;
constexpr int kTasks = 8192;             // 32768 batches / 4 per task
constexpr int kCTA   = 128;              // 4 warps
constexpr int kGrid  = 296;              // 1184 warps
constexpr int kWarps = kGrid * (kCTA / 32);
}

__device__ __forceinline__ u64 pack2(float lo, float hi) {
    u64 r; asm("mov.b64 %0, {%1, %2};" : "=l"(r) : "f"(lo), "f"(hi)); return r;
}
__device__ __forceinline__ void unpack2(u64 v, float& lo, float& hi) {
    asm("mov.b64 {%0, %1}, %2;" : "=f"(lo), "=f"(hi) : "l"(v));
}
__device__ __forceinline__ u64 fma2(u64 a, u64 b, u64 c) {
    u64 d; asm("fma.rn.f32x2 %0, %1, %2, %3;" : "=l"(d) : "l"(a), "l"(b), "l"(c)); return d;
}
__device__ __forceinline__ float ex2a(float x) {
    float r; asm("ex2.approx.f32 %0, %1;" : "=f"(r) : "f"(x)); return r;
}
__device__ __forceinline__ float rcpa(float x) {
    float r; asm("rcp.approx.f32 %0, %1;" : "=f"(r) : "f"(x)); return r;
}
__device__ __forceinline__ float sig_fast(float x) {   // exact saturation at +/-inf
    return rcpa(1.0f + ex2a(-1.4426950408889634f * x));
}
__device__ __forceinline__ float tanh_fast(float x) {
    return fmaf(-2.0f, rcpa(1.0f + ex2a(2.8853900817779268f * x)), 1.0f);
}
__device__ __forceinline__ uint32_t smem_u32(const void* p) {
    return (uint32_t)__cvta_generic_to_shared(p);
}
__device__ __forceinline__ void sts32(uint32_t a, float v) {
    asm volatile("st.shared.f32 [%0], %1;" :: "r"(a), "f"(v));
}
__device__ __forceinline__ void lds128(uint32_t a, u64& x, u64& y) {
    asm volatile("ld.shared.v2.u64 {%0,%1}, [%2];" : "=l"(x), "=l"(y) : "r"(a));
}
__device__ __forceinline__ float redsum(float v) {   // xor butterfly, all lanes get sum
#pragma unroll
    for (int m = 16; m >= 1; m >>= 1) v += __shfl_xor_sync(0xffffffffu, v, m);
    return v;
}

__global__ void __launch_bounds__(kCTA)
gru_decoder_kernel(const float* __restrict__ feat,      // [B,T,F]
                   const float* __restrict__ init_in,   // [B,1]
                   const float* __restrict__ init_h,    // [B,H]
                   const float* __restrict__ kern,      // [1+F, 3H]
                   const float* __restrict__ rker,      // [H, 3H]
                   const float* __restrict__ bx,        // [3H]
                   const float* __restrict__ bh,        // [3H]
                   const float* __restrict__ dw,        // [H,1]
                   const float* __restrict__ db,        // [1]
                   float* __restrict__ out)             // [B,T,1]
{
    // Per-warp broadcast buffers, double-buffered:
    // shH[w][buf][b][j] : hidden state of batch b (32 floats = 128 B row)
    // shX[w][buf][b][k] : features of batch b   (16 floats =  64 B row)
    __shared__ __align__(16) float shH[4][2][4][kH];
    __shared__ __align__(16) float shX[4][2][4][kF];

    const int tid  = threadIdx.x;
    const int wip  = tid >> 5;
    const int lane = tid & 31;

    // k-pair-packed weights (contiguous along k -> no dup MOVs at use site).
    u64 Rz2[kH / 2], Rr2[kH / 2], Rh2[kH / 2];
#pragma unroll
    for (int q = 0; q < kH / 2; q++) {
        Rz2[q] = pack2(rker[(2 * q) * 96 + lane],          rker[(2 * q + 1) * 96 + lane]);
        Rr2[q] = pack2(rker[(2 * q) * 96 + kH + lane],     rker[(2 * q + 1) * 96 + kH + lane]);
        Rh2[q] = pack2(rker[(2 * q) * 96 + 2 * kH + lane], rker[(2 * q + 1) * 96 + 2 * kH + lane]);
    }
    u64 Wz2[kF / 2], Wr2[kF / 2], Wx2[kF / 2];   // feature rows 1..16 of kern
#pragma unroll
    for (int q = 0; q < kF / 2; q++) {
        Wz2[q] = pack2(kern[(2 * q + 1) * 96 + lane],          kern[(2 * q + 2) * 96 + lane]);
        Wr2[q] = pack2(kern[(2 * q + 1) * 96 + kH + lane],     kern[(2 * q + 2) * 96 + kH + lane]);
        Wx2[q] = pack2(kern[(2 * q + 1) * 96 + 2 * kH + lane], kern[(2 * q + 2) * 96 + 2 * kH + lane]);
    }
    const float Wz0 = kern[lane];                 // prev_out row (kern row 0)
    const float Wr0 = kern[kH + lane];
    const float Wx0 = kern[2 * kH + lane];
    const float bz  = bx[lane] + bh[lane];
    const float br  = bx[kH + lane] + bh[kH + lane];
    const float bxv = bx[2 * kH + lane];
    const float bhv = bh[2 * kH + lane];
    const float dwl = dw[lane];
    const float dbv = db[0];

    // Bias folded into accumulator init: {bias, 0} (horizontal add fixes it).
    const u64 bz2i = pack2(bz, 0.0f);
    const u64 br2i = pack2(br, 0.0f);
    const u64 bx2i = pack2(bxv, 0.0f);
    const u64 bh2i = pack2(bhv, 0.0f);

    const uint32_t baseH = smem_u32(&shH[wip][0][0][0]);
    const uint32_t baseX = smem_u32(&shX[wip][0][0][0]);

    const int wg = (blockIdx.x * kCTA + tid) >> 5;

#pragma unroll 1
    for (int task = wg; task < kTasks; task += kWarps) {
        const int b0 = 4 * task;

        float h[4], pinit[4], fv[4];
#pragma unroll
        for (int b = 0; b < 4; b++) {
            h[b]     = init_h[(size_t)(b0 + b) * kH + lane];
            pinit[b] = init_in[b0 + b];
            fv[b]    = 0.0f;
            if (lane < kF) fv[b] = feat[(size_t)(b0 + b) * kT * kF + lane];
        }

#pragma unroll 1
        for (int t = 0; t < kT; t++) {
            const uint32_t bufH = baseH + (uint32_t)(t & 1) * (4 * kH * 4);
            const uint32_t bufX = baseX + (uint32_t)(t & 1) * (4 * kF * 4);

            // Publish my state + staged features.
#pragma unroll
            for (int b = 0; b < 4; b++) {
                sts32(bufH + (uint32_t)(b * kH + lane) * 4, h[b]);
                if (lane < kF) sts32(bufX + (uint32_t)(b * kF + lane) * 4, fv[b]);
            }
            __syncwarp();

            // Dense(1) reduction for the PREVIOUS state (o_{t-1}); 5-SHFL
            // chains issue now and complete under the GEMM below.
            float op[4];
#pragma unroll
            for (int b = 0; b < 4; b++) op[b] = redsum(h[b] * dwl);

            // Load next step's features (latency covered by mainloop).
            if (lane < kF) {
                int tn = (t + 1 < kT) ? t + 1 : t;
#pragma unroll
                for (int b = 0; b < 4; b++)
                    fv[b] = feat[(size_t)(b0 + b) * kT * kF + tn * kF + lane];
            }

            u64 az2[4], ar2[4], ah2[4], ax2[4];
#pragma unroll
            for (int b = 0; b < 4; b++) {
                az2[b] = bz2i; ar2[b] = br2i; ah2[b] = bh2i; ax2[b] = bx2i;
            }

            // Recurrent part: broadcast LDS.128 = 2 k-pairs, feeds 3 gates.
#pragma unroll
            for (int q = 0; q < kH / 4; q++) {
#pragma unroll
                for (int b = 0; b < 4; b++) {
                    u64 p0, p1;
                    lds128(bufH + (uint32_t)(b * kH + 4 * q) * 4, p0, p1);
                    az2[b] = fma2(p0, Rz2[2 * q],     az2[b]);
                    ar2[b] = fma2(p0, Rr2[2 * q],     ar2[b]);
                    ah2[b] = fma2(p0, Rh2[2 * q],     ah2[b]);
                    az2[b] = fma2(p1, Rz2[2 * q + 1], az2[b]);
                    ar2[b] = fma2(p1, Rr2[2 * q + 1], ar2[b]);
                    ah2[b] = fma2(p1, Rh2[2 * q + 1], ah2[b]);
                }
            }
            // Feature part.
#pragma unroll
            for (int q = 0; q < kF / 4; q++) {
#pragma unroll
                for (int b = 0; b < 4; b++) {
                    u64 p0, p1;
                    lds128(bufX + (uint32_t)(b * kF + 4 * q) * 4, p0, p1);
                    az2[b] = fma2(p0, Wz2[2 * q],     az2[b]);
                    ar2[b] = fma2(p0, Wr2[2 * q],     ar2[b]);
                    ax2[b] = fma2(p0, Wx2[2 * q],     ax2[b]);
                    az2[b] = fma2(p1, Wz2[2 * q + 1], az2[b]);
                    ar2[b] = fma2(p1, Wr2[2 * q + 1], ar2[b]);
                    ax2[b] = fma2(p1, Wx2[2 * q + 1], ax2[b]);
                }
            }

            // Epilogue per batch: o_prev, fold pairs, activations, new state.
#pragma unroll
            for (int b = 0; b < 4; b++) {
                float o_prev = (t == 0) ? pinit[b] : (op[b] + dbv);
                if (t > 0 && lane == 0) out[(size_t)(b0 + b) * kT + (t - 1)] = op[b] + dbv;

                float lo, hi;
                unpack2(az2[b], lo, hi);
                float az = fmaf(Wz0, o_prev, lo + hi);
                unpack2(ar2[b], lo, hi);
                float ar = fmaf(Wr0, o_prev, lo + hi);
                unpack2(ax2[b], lo, hi);
                float ax = fmaf(Wx0, o_prev, lo + hi);
                unpack2(ah2[b], lo, hi);
                float ah = lo + hi;

                float z = sig_fast(az);
                float r = sig_fast(ar);
                float hh = tanh_fast(fmaf(r, ah, ax));
                h[b] = fmaf(z, h[b] - hh, hh);
            }
        }

        // Final outputs o_{T-1} (one redsum per batch, once per task).
#pragma unroll
        for (int b = 0; b < 4; b++) {
            float o = redsum(h[b] * dwl) + dbv;
            if (lane == 0) out[(size_t)(b0 + b) * kT + (kT - 1)] = o;
        }
    }
}

extern "C" void kernel_launch(void* const* d_in, const int* in_sizes, int n_in,
                              void* d_out, int out_size) {
    (void)in_sizes; (void)n_in; (void)out_size;
    gru_decoder_kernel<<<kGrid, kCTA>>>(
        (const float*)d_in[0],   // decoder_feature
        (const float*)d_in[1],   // decoder_init_input
        (const float*)d_in[2],   // init_state
        (const float*)d_in[3],   // kernel
        (const float*)d_in[4],   // recurrent_kernel
        (const float*)d_in[5],   // bias_x
        (const float*)d_in[6],   // bias_h
        (const float*)d_in[7],   // dense_w
        (const float*)d_in[8],   // dense_b
        (float*)d_out);
}

// round 8
// speedup vs baseline: 1.2081x; 1.2037x over previous
#include <cuda_runtime.h>
#include <cstdint>

// GRU decoder (Keras reset_after=True), B=32768, T=48, F=16, H=32, fp32.
// R5 structure (batch-packed f32x2, lane j = neuron j, 4 batches/warp via two
// pairs A/B, h/features broadcast through per-warp shared buffers) with the
// register footprint cut to fit 3 CTAs/SM (12 warps): Rz/Rr stay in RF;
// Rh + all input-part weights move to shared, read per-lane (conflict-free
// 128B rows, 1 wavefront each).

typedef unsigned long long u64;

namespace {
constexpr int kT     = 48;
constexpr int kF     = 16;
constexpr int kH     = 32;
constexpr int kTasks = 8192;             // 32768 batches / 4 per task
constexpr int kCTA   = 128;              // 4 warps
constexpr int kGrid  = 444;              // 3 CTAs/SM on 148 SMs, one wave
constexpr int kWarps = kGrid * (kCTA / 32);
}

__device__ __forceinline__ u64 pack2(float lo, float hi) {
    u64 r; asm("mov.b64 %0, {%1, %2};" : "=l"(r) : "f"(lo), "f"(hi)); return r;
}
__device__ __forceinline__ void unpack2(u64 v, float& lo, float& hi) {
    asm("mov.b64 {%0, %1}, %2;" : "=f"(lo), "=f"(hi) : "l"(v));
}
__device__ __forceinline__ u64 fma2(u64 a, u64 b, u64 c) {
    u64 d; asm("fma.rn.f32x2 %0, %1, %2, %3;" : "=l"(d) : "l"(a), "l"(b), "l"(c)); return d;
}
__device__ __forceinline__ float ex2a(float x) {
    float r; asm("ex2.approx.f32 %0, %1;" : "=f"(r) : "f"(x)); return r;
}
__device__ __forceinline__ float rcpa(float x) {
    float r; asm("rcp.approx.f32 %0, %1;" : "=f"(r) : "f"(x)); return r;
}
__device__ __forceinline__ float sig_fast(float x) {   // exact saturation at +/-inf
    return rcpa(1.0f + ex2a(-1.4426950408889634f * x));
}
__device__ __forceinline__ float tanh_fast(float x) {
    return fmaf(-2.0f, rcpa(1.0f + ex2a(2.8853900817779268f * x)), 1.0f);
}
__device__ __forceinline__ uint32_t smem_u32(const void* p) {
    return (uint32_t)__cvta_generic_to_shared(p);
}
__device__ __forceinline__ void sts128(uint32_t a, float x, float y, float z, float w) {
    asm volatile("st.shared.v4.f32 [%0], {%1,%2,%3,%4};"
                 :: "r"(a), "f"(x), "f"(y), "f"(z), "f"(w));
}
__device__ __forceinline__ void lds128(uint32_t a, u64& x, u64& y) {
    asm volatile("ld.shared.v2.u64 {%0,%1}, [%2];" : "=l"(x), "=l"(y) : "r"(a));
}
__device__ __forceinline__ float redsum(float v) {   // xor butterfly, all lanes get sum
#pragma unroll
    for (int m = 16; m >= 1; m >>= 1) v += __shfl_xor_sync(0xffffffffu, v, m);
    return v;
}

__global__ void __launch_bounds__(kCTA, 3)
gru_decoder_kernel(const float* __restrict__ feat,      // [B,T,F]
                   const float* __restrict__ init_in,   // [B,1]
                   const float* __restrict__ init_h,    // [B,H]
                   const float* __restrict__ kern,      // [1+F, 3H]
                   const float* __restrict__ rker,      // [H, 3H]
                   const float* __restrict__ bx,        // [3H]
                   const float* __restrict__ bh,        // [3H]
                   const float* __restrict__ dw,        // [H,1]
                   const float* __restrict__ db,        // [1]
                   float* __restrict__ out)             // [B,T,1]
{
    // Constant weight tables (per-lane-distinct reads, 128B rows -> 1 wf):
    // sWin[g][k][j] = kern[k][g*32+j]  (k=0: prev_out row; k=1..16: features)
    // sRh[k][j]     = rker[k][64+j]    (hh-gate recurrent)
    __shared__ float sWin[3][17][kH];
    __shared__ float sRh[kH][kH];
    // Per-warp broadcast buffers, double-buffered:
    // shH[w][buf][j] = {hA0,hA1,hB0,hB1} of lane j
    // shX[w][buf][k] = {fA0,fA1,fB0,fB1} of feature k
    __shared__ __align__(16) float shH[4][2][kH][4];
    __shared__ __align__(16) float shX[4][2][kF][4];

    const int tid  = threadIdx.x;
    const int wip  = tid >> 5;
    const int lane = tid & 31;

    for (int i = tid; i < 17 * 96; i += kCTA) {
        int k = i / 96, c = i % 96;
        sWin[c / kH][k][c % kH] = kern[i];
    }
    for (int i = tid; i < kH * kH; i += kCTA) {
        int k = i / kH, j = i % kH;
        sRh[k][j] = rker[k * 96 + 2 * kH + j];
    }
    __syncthreads();

    // Register-stationary recurrent weights for z and r gates.
    float Rz[kH], Rr[kH];
#pragma unroll
    for (int k = 0; k < kH; k++) {
        Rz[k] = rker[k * 96 + lane];
        Rr[k] = rker[k * 96 + kH + lane];
    }
    const float bzv = bx[lane] + bh[lane];
    const float brv = bx[kH + lane] + bh[kH + lane];
    const u64 bz2 = pack2(bzv, bzv);
    const u64 br2 = pack2(brv, brv);
    const u64 bx2 = pack2(bx[2 * kH + lane], bx[2 * kH + lane]);
    const u64 bh2 = pack2(bh[2 * kH + lane], bh[2 * kH + lane]);
    const float dwl = dw[lane];
    const float dbv = db[0];

    const uint32_t baseH = smem_u32(&shH[wip][0][0][0]);
    const uint32_t baseX = smem_u32(&shX[wip][0][0][0]);

    const int wg = (blockIdx.x * kCTA + tid) >> 5;

#pragma unroll 1
    for (int task = wg; task < kTasks; task += kWarps) {
        const int b0 = 4 * task, b1 = b0 + 1, b2 = b0 + 2, b3 = b0 + 3;

        float hA0 = init_h[(size_t)b0 * kH + lane];
        float hA1 = init_h[(size_t)b1 * kH + lane];
        float hB0 = init_h[(size_t)b2 * kH + lane];
        float hB1 = init_h[(size_t)b3 * kH + lane];
        u64 prevA = pack2(init_in[b0], init_in[b1]);
        u64 prevB = pack2(init_in[b2], init_in[b3]);

        const float* f0 = feat + (size_t)b0 * kT * kF;
        const float* f1 = feat + (size_t)b1 * kT * kF;
        const float* f2 = feat + (size_t)b2 * kT * kF;
        const float* f3 = feat + (size_t)b3 * kT * kF;
        float* ob = out + (size_t)b0 * kT;

        float fv0 = 0.f, fv1 = 0.f, fv2 = 0.f, fv3 = 0.f;
        if (lane < kF) {
            fv0 = f0[lane]; fv1 = f1[lane]; fv2 = f2[lane]; fv3 = f3[lane];
        }

#pragma unroll 1
        for (int t = 0; t < kT; t++) {
            const uint32_t bufH = baseH + (uint32_t)(t & 1) * (kH * 16);
            const uint32_t bufX = baseX + (uint32_t)(t & 1) * (kF * 16);

            // Publish my state + staged features.
            sts128(bufH + lane * 16, hA0, hA1, hB0, hB1);
            if (lane < kF) sts128(bufX + lane * 16, fv0, fv1, fv2, fv3);
            __syncwarp();

            // Next step's features (latency covered by the mainloop).
            if (lane < kF) {
                int tn = (t + 1 < kT) ? t + 1 : t;
                fv0 = f0[tn * kF + lane]; fv1 = f1[tn * kF + lane];
                fv2 = f2[tn * kF + lane]; fv3 = f3[tn * kF + lane];
            }

            u64 azA = bz2, azB = bz2;
            u64 arA = br2, arB = br2;
            u64 axA = bx2, axB = bx2;
            u64 ahA = bh2, ahB = bh2;

            // Recurrent part: broadcast LDS for h; Rz/Rr dup'd from RF,
            // Rh read per-lane from shared.
#pragma unroll
            for (int k = 0; k < kH; k++) {
                u64 hkA, hkB;
                lds128(bufH + k * 16, hkA, hkB);
                u64 wz = pack2(Rz[k], Rz[k]);
                u64 wr = pack2(Rr[k], Rr[k]);
                float rh = sRh[k][lane];
                u64 wh = pack2(rh, rh);
                azA = fma2(hkA, wz, azA); azB = fma2(hkB, wz, azB);
                arA = fma2(hkA, wr, arA); arB = fma2(hkB, wr, arB);
                ahA = fma2(hkA, wh, ahA); ahB = fma2(hkB, wh, ahB);
            }
            // prev_out term (weights row 0 from shared).
            {
                float w0 = sWin[0][0][lane];
                float w1 = sWin[1][0][lane];
                float w2 = sWin[2][0][lane];
                u64 wz = pack2(w0, w0);
                u64 wr = pack2(w1, w1);
                u64 wx = pack2(w2, w2);
                azA = fma2(prevA, wz, azA); azB = fma2(prevB, wz, azB);
                arA = fma2(prevA, wr, arA); arB = fma2(prevB, wr, arB);
                axA = fma2(prevA, wx, axA); axB = fma2(prevB, wx, axB);
            }
            // Feature part: broadcast LDS for x; weights per-lane from shared.
#pragma unroll
            for (int k = 0; k < kF; k++) {
                u64 xkA, xkB;
                lds128(bufX + k * 16, xkA, xkB);
                float w0 = sWin[0][k + 1][lane];
                float w1 = sWin[1][k + 1][lane];
                float w2 = sWin[2][k + 1][lane];
                u64 wz = pack2(w0, w0);
                u64 wr = pack2(w1, w1);
                u64 wx = pack2(w2, w2);
                azA = fma2(xkA, wz, azA); azB = fma2(xkB, wz, azB);
                arA = fma2(xkA, wr, arA); arB = fma2(xkB, wr, arB);
                axA = fma2(xkA, wx, axA); axB = fma2(xkB, wx, axB);
            }

            // Activations + state update.
            float z0, z1, r0, r1, x0, x1, g0, g1;
            unpack2(azA, z0, z1); unpack2(arA, r0, r1);
            unpack2(axA, x0, x1); unpack2(ahA, g0, g1);
            z0 = sig_fast(z0); z1 = sig_fast(z1);
            r0 = sig_fast(r0); r1 = sig_fast(r1);
            float hh0 = tanh_fast(fmaf(r0, g0, x0));
            float hh1 = tanh_fast(fmaf(r1, g1, x1));
            hA0 = fmaf(z0, hA0 - hh0, hh0);
            hA1 = fmaf(z1, hA1 - hh1, hh1);

            unpack2(azB, z0, z1); unpack2(arB, r0, r1);
            unpack2(axB, x0, x1); unpack2(ahB, g0, g1);
            z0 = sig_fast(z0); z1 = sig_fast(z1);
            r0 = sig_fast(r0); r1 = sig_fast(r1);
            hh0 = tanh_fast(fmaf(r0, g0, x0));
            hh1 = tanh_fast(fmaf(r1, g1, x1));
            hB0 = fmaf(z0, hB0 - hh0, hh0);
            hB1 = fmaf(z1, hB1 - hh1, hh1);

            // Dense(1): butterfly-reduce; every lane ends with the sums.
            float oA0 = redsum(hA0 * dwl) + dbv;
            float oA1 = redsum(hA1 * dwl) + dbv;
            float oB0 = redsum(hB0 * dwl) + dbv;
            float oB1 = redsum(hB1 * dwl) + dbv;
            prevA = pack2(oA0, oA1);
            prevB = pack2(oB0, oB1);
            if (lane == 0) {
                ob[t]          = oA0;
                ob[kT + t]     = oA1;
                ob[2 * kT + t] = oB0;
                ob[3 * kT + t] = oB1;
            }
        }
    }
}

extern "C" void kernel_launch(void* const* d_in, const int* in_sizes, int n_in,
                              void* d_out, int out_size) {
    (void)in_sizes; (void)n_in; (void)out_size;
    gru_decoder_kernel<<<kGrid, kCTA>>>(
        (const float*)d_in[0],   // decoder_feature
        (const float*)d_in[1],   // decoder_init_input
        (const float*)d_in[2],   // init_state
        (const float*)d_in[3],   // kernel
        (const float*)d_in[4],   // recurrent_kernel
        (const float*)d_in[5],   // bias_x
        (const float*)d_in[6],   // bias_h
        (const float*)d_in[7],   // dense_w
        (const float*)d_in[8],   // dense_b
        (float*)d_out);
}